// round 7
// baseline (speedup 1.0000x reference)
#include <cuda_runtime.h>
#include <cstdint>

// Problem constants
#define BATCH 2
#define SEQ   2048
#define DIM   1024
#define NH    16
#define HD    64
#define MROWS (BATCH * SEQ)   // 4096

// Scratch (allocation-free rule: __device__ globals)
__device__ float g_Q[BATCH * NH * SEQ * HD];   // [b,h,s,hd] (tf32-rounded)
__device__ float g_K[BATCH * NH * SEQ * HD];   // (tf32-rounded)
__device__ float g_V[BATCH * NH * SEQ * HD];   // (tf32-rounded)
__device__ float g_A[BATCH * SEQ * DIM];       // attn out [b,s,h*hd] (tf32-rounded)
__device__ float g_Wc[4 * DIM * DIM];          // tf32-rounded Wq,Wk,Wv,Wo
__device__ float g_Xc[3 * MROWS * DIM];        // tf32-rounded q,k,v

// ---------------------------------------------------------------------------
// Helpers
// ---------------------------------------------------------------------------
__device__ __forceinline__ uint32_t smem_u32(const void* p) {
    uint32_t a;
    asm("{ .reg .u64 t; cvta.to.shared.u64 t, %1; cvt.u32.u64 %0, t; }" : "=r"(a) : "l"(p));
    return a;
}

#define CP_ASYNC16(dst, src) \
    asm volatile("cp.async.cg.shared.global [%0], [%1], 16;" :: "r"(dst), "l"(src))
#define CP_ASYNC4(dst, src) \
    asm volatile("cp.async.ca.shared.global [%0], [%1], 4;" :: "r"(dst), "l"(src))
#define CP_ASYNC_COMMIT() asm volatile("cp.async.commit_group;" ::: "memory")
#define CP_ASYNC_WAIT(n)  asm volatile("cp.async.wait_group %0;" :: "n"(n) : "memory")

__device__ __forceinline__ uint32_t f2tf32(float x) {
    uint32_t r;
    asm("cvt.rna.tf32.f32 %0, %1;" : "=r"(r) : "f"(x));
    return r;
}

#define MMA_TF32(d, av, bv)                                                   \
    asm volatile("mma.sync.aligned.m16n8k8.row.col.f32.tf32.tf32.f32 "        \
                 "{%0,%1,%2,%3}, {%4,%5,%6,%7}, {%8,%9}, {%0,%1,%2,%3};"      \
                 : "+f"((d)[0]), "+f"((d)[1]), "+f"((d)[2]), "+f"((d)[3])     \
                 : "r"((av)[0]), "r"((av)[1]), "r"((av)[2]), "r"((av)[3]),    \
                   "r"((bv)[0]), "r"((bv)[1]))

// Fast exp2 on the FMA pipe. Rel err ~3e-6.
__device__ __forceinline__ float fast_exp2(float x) {
    x = fmaxf(x, -126.0f);
    float t = x + 12582912.0f;            // 2^23 + 2^22
    float i = t - 12582912.0f;
    float f = x - i;
    float p = 1.3333558e-3f;
    p = fmaf(p, f, 9.6181291e-3f);
    p = fmaf(p, f, 5.5504109e-2f);
    p = fmaf(p, f, 2.4022651e-1f);
    p = fmaf(p, f, 6.9314718e-1f);
    p = fmaf(p, f, 1.0f);
    int ib = __float_as_int(t) << 23;     // == i << 23 exactly
    return __int_as_float(__float_as_int(p) + ib);
}

// ---------------------------------------------------------------------------
// Fused tf32 rounding pre-pass: all 7 arrays in ONE launch.
// grid = (1024, 7); blockIdx.y selects the segment. MLP=4 per thread.
// ---------------------------------------------------------------------------
struct ConvArgs {
    const float* src[7];
    float* dst[7];
    int n4[7];
};

__global__ __launch_bounds__(256) void conv_tf32_all(ConvArgs a) {
    const int seg = blockIdx.y;
    const float* src = a.src[seg];
    float* dst = a.dst[seg];
    const int n4 = a.n4[seg];
    int i0 = blockIdx.x * 1024 + threadIdx.x;
    if (i0 >= n4) return;
    float4 v[4];
    int idx[4];
#pragma unroll
    for (int t = 0; t < 4; t++) {
        idx[t] = i0 + t * 256;
        if (idx[t] < n4) v[t] = ((const float4*)src)[idx[t]];
    }
#pragma unroll
    for (int t = 0; t < 4; t++) {
        if (idx[t] < n4) {
            float4 r;
            r.x = __uint_as_float(f2tf32(v[t].x));
            r.y = __uint_as_float(f2tf32(v[t].y));
            r.z = __uint_as_float(f2tf32(v[t].z));
            r.w = __uint_as_float(f2tf32(v[t].w));
            ((float4*)dst)[idx[t]] = r;
        }
    }
}

// ---------------------------------------------------------------------------
// tf32 mma.sync GEMM: C = A @ W^T + bias. Pre-rounded tf32 inputs.
// CTA tile 128x256, BK=32, 512 threads = 16 warps (4 m x 4 n), 32x64 each.
// 16 warps/SM for latency hiding. XOR-swizzled smem.
// ---------------------------------------------------------------------------
#define GBM 128
#define GBN 256
#define GBK 32
#define NKT (DIM / GBK)                 // 32
#define SA_BYTES (GBM * GBK * 4)        // 16384
#define SB_BYTES (GBN * GBK * 4)        // 32768
#define SM_GEMM_TOTAL (2 * (SA_BYTES + SB_BYTES))   // 98304

struct GemmArgs {
    const float* A;
    const float* W;
    const float* bias;
    float* C;
};

template <int SPLIT_HEADS>
__device__ __forceinline__ void gemm_body(const float* __restrict__ A,
                                          const float* __restrict__ W,
                                          const float* __restrict__ bias,
                                          float* __restrict__ C) {
    extern __shared__ char smem[];
    const float* sAf = (const float*)smem;               // [2][128][32]
    const float* sBf = (const float*)(smem + 2 * SA_BYTES);
    const uint32_t sA = smem_u32(smem);
    const uint32_t sB = sA + 2 * SA_BYTES;

    const int tid = threadIdx.x;
    const int lane = tid & 31;
    const int wid = tid >> 5;      // 0..15
    const int wm = wid & 3;        // 0..3 (m: 4 x 32 = 128)
    const int wn = wid >> 2;       // 0..3 (n: 4 x 64 = 256)
    const int g = lane >> 2;
    const int tig = lane & 3;
    const int m0 = blockIdx.y * GBM;
    const int n0 = blockIdx.x * GBN;

    float acc[2][8][4];
#pragma unroll
    for (int i = 0; i < 2; i++)
#pragma unroll
        for (int j = 0; j < 8; j++)
#pragma unroll
            for (int c = 0; c < 4; c++) acc[i][j][c] = 0.f;

    auto stage = [&](int kt, int buf) {
        const int k0 = kt * GBK;
#pragma unroll
        for (int t = 0; t < 2; t++) {
            int idx = tid + t * 512;
            int row = idx >> 3;
            int c = idx & 7;
            uint32_t dst = sA + buf * SA_BYTES + row * 128 + ((c ^ (row & 7)) << 4);
            CP_ASYNC16(dst, &A[(size_t)(m0 + row) * DIM + k0 + c * 4]);
        }
#pragma unroll
        for (int t = 0; t < 4; t++) {
            int idx = tid + t * 512;
            int row = idx >> 3;
            int c = idx & 7;
            uint32_t dst = sB + buf * SB_BYTES + row * 128 + ((c ^ (row & 7)) << 4);
            CP_ASYNC16(dst, &W[(size_t)(n0 + row) * DIM + k0 + c * 4]);
        }
    };

    stage(0, 0);
    CP_ASYNC_COMMIT();

    for (int kt = 0; kt < NKT; kt++) {
        if (kt + 1 < NKT) {
            stage(kt + 1, (kt + 1) & 1);
            CP_ASYNC_COMMIT();
            CP_ASYNC_WAIT(1);
        } else {
            CP_ASYNC_WAIT(0);
        }
        __syncthreads();

        const float* Ab = sAf + (kt & 1) * (SA_BYTES / 4);
        const float* Bb = sBf + (kt & 1) * (SB_BYTES / 4);
#pragma unroll
        for (int s = 0; s < 4; s++) {
            const int k1 = s * 8 + tig;
            const int k2 = k1 + 4;
            uint32_t a[2][4];
#pragma unroll
            for (int i = 0; i < 2; i++) {
                int r1 = wm * 32 + i * 16 + g;
                int r2 = r1 + 8;
                a[i][0] = __float_as_uint(Ab[r1 * 32 + (k1 ^ ((r1 & 7) << 2))]);
                a[i][1] = __float_as_uint(Ab[r2 * 32 + (k1 ^ ((r2 & 7) << 2))]);
                a[i][2] = __float_as_uint(Ab[r1 * 32 + (k2 ^ ((r1 & 7) << 2))]);
                a[i][3] = __float_as_uint(Ab[r2 * 32 + (k2 ^ ((r2 & 7) << 2))]);
            }
            uint32_t bf[8][2];
#pragma unroll
            for (int j = 0; j < 8; j++) {
                int rn = wn * 64 + j * 8 + g;
                bf[j][0] = __float_as_uint(Bb[rn * 32 + (k1 ^ ((rn & 7) << 2))]);
                bf[j][1] = __float_as_uint(Bb[rn * 32 + (k2 ^ ((rn & 7) << 2))]);
            }
#pragma unroll
            for (int i = 0; i < 2; i++)
#pragma unroll
                for (int j = 0; j < 8; j++) MMA_TF32(acc[i][j], a[i], bf[j]);
        }
        __syncthreads();
    }

#pragma unroll
    for (int i = 0; i < 2; i++) {
        const int m1 = m0 + wm * 32 + i * 16 + g;
        const int m2 = m1 + 8;
#pragma unroll
        for (int j = 0; j < 8; j++) {
            const int n = n0 + wn * 64 + j * 8 + tig * 2;
            const float2 bb = *(const float2*)&bias[n];
            float2 r1, r2;
            if (SPLIT_HEADS) {
                r1.x = __uint_as_float(f2tf32(acc[i][j][0] + bb.x));
                r1.y = __uint_as_float(f2tf32(acc[i][j][1] + bb.y));
                r2.x = __uint_as_float(f2tf32(acc[i][j][2] + bb.x));
                r2.y = __uint_as_float(f2tf32(acc[i][j][3] + bb.y));
                int h = n >> 6;
                int hd = n & (HD - 1);
                {
                    int b = m1 >> 11, sq = m1 & (SEQ - 1);
                    *(float2*)&C[((size_t)((b * NH + h) * SEQ + sq)) * HD + hd] = r1;
                }
                {
                    int b = m2 >> 11, sq = m2 & (SEQ - 1);
                    *(float2*)&C[((size_t)((b * NH + h) * SEQ + sq)) * HD + hd] = r2;
                }
            } else {
                r1.x = acc[i][j][0] + bb.x;
                r1.y = acc[i][j][1] + bb.y;
                r2.x = acc[i][j][2] + bb.x;
                r2.y = acc[i][j][3] + bb.y;
                *(float2*)&C[(size_t)m1 * DIM + n] = r1;
                *(float2*)&C[(size_t)m2 * DIM + n] = r2;
            }
        }
    }
}

__global__ __launch_bounds__(512, 1) void gemm_qkv(GemmArgs a0, GemmArgs a1, GemmArgs a2) {
    const GemmArgs& a = (blockIdx.z == 0) ? a0 : (blockIdx.z == 1) ? a1 : a2;
    gemm_body<1>(a.A, a.W, a.bias, a.C);
}

__global__ __launch_bounds__(512, 1) void gemm_out(const float* __restrict__ A,
                                                   const float* __restrict__ W,
                                                   const float* __restrict__ bias,
                                                   float* __restrict__ C) {
    gemm_body<0>(A, W, bias, C);
}

// ---------------------------------------------------------------------------
// Tensor-core flash attention (tf32 mma.sync), M=32 rows per warp.
// 128 thr (4 warps) = 128 q-rows/CTA; each K/V fragment feeds 2 MMAs.
// smem 111KB -> 2 CTAs/SM. KV double-buffered via cp.async. (unchanged)
// ---------------------------------------------------------------------------
#define FKT 64
#define KVS 72          // smem row stride (floats)
#define FNT (SEQ / FKT) // 32

#define F_KSM 0
#define F_VSM (2 * FKT * KVS)                 // 9216
#define F_PSM (F_VSM + 2 * FKT * KVS)         // 18432
#define F_MSK (F_PSM + 128 * KVS)             // 27648 (int region)
#define F_TOTAL_FLOATS (F_MSK + 2 * FKT)      // 27776
#define FLASH_SMEM_BYTES (F_TOTAL_FLOATS * 4) // 111104

#define CS 0.18033688f  // 0.125 * log2(e)

__global__ __launch_bounds__(128) void flash_attn_tc(const int* __restrict__ mask,
                                                     float* __restrict__ Out) {
    extern __shared__ char smem[];
    float* smf = (float*)smem;
    int* smi = (int*)smem;
    const uint32_t sbase = smem_u32(smem);

    const int b = blockIdx.z;
    const int h = blockIdx.y;
    const int tid = threadIdx.x;
    const int w = tid >> 5;
    const int lane = tid & 31;
    const int g = lane >> 2;       // 0..7
    const int tig = lane & 3;      // 0..3
    const int qr0 = blockIdx.x * 128 + w * 32;

    const float* Qp = g_Q + ((size_t)((b * NH + h) * SEQ) + qr0) * HD;
    const float* Kb = g_K + ((size_t)((b * NH + h) * SEQ)) * HD;
    const float* Vb = g_V + ((size_t)((b * NH + h) * SEQ)) * HD;
    const int* mb = mask + b * SEQ;

    uint32_t aQ[2][8][4];
#pragma unroll
    for (int mi = 0; mi < 2; mi++) {
        const float* Qm = Qp + (size_t)(16 * mi) * HD;
#pragma unroll
        for (int s = 0; s < 8; s++) {
            aQ[mi][s][0] = __float_as_uint(Qm[g * HD + 8 * s + tig]);
            aQ[mi][s][1] = __float_as_uint(Qm[(g + 8) * HD + 8 * s + tig]);
            aQ[mi][s][2] = __float_as_uint(Qm[g * HD + 8 * s + tig + 4]);
            aQ[mi][s][3] = __float_as_uint(Qm[(g + 8) * HD + 8 * s + tig + 4]);
        }
    }

    float oacc[2][8][4];
#pragma unroll
    for (int mi = 0; mi < 2; mi++)
#pragma unroll
        for (int j = 0; j < 8; j++)
#pragma unroll
            for (int c = 0; c < 4; c++) oacc[mi][j][c] = 0.f;
    float mrun[4] = {-1e30f, -1e30f, -1e30f, -1e30f};
    float lrun[4] = {0.f, 0.f, 0.f, 0.f};

    auto stage = [&](int kt, int buf) {
        const float* Kg = Kb + (size_t)kt * FKT * HD;
        const float* Vg = Vb + (size_t)kt * FKT * HD;
        const uint32_t dK = sbase + (F_KSM + buf * FKT * KVS) * 4;
        const uint32_t dV = sbase + (F_VSM + buf * FKT * KVS) * 4;
#pragma unroll
        for (int t = 0; t < 8; t++) {
            int idx = tid + t * 128;       // 0..1023
            int row = idx >> 4;
            int c = idx & 15;
            CP_ASYNC16(dK + row * (KVS * 4) + c * 16, &Kg[row * HD + c * 4]);
            CP_ASYNC16(dV + row * (KVS * 4) + c * 16, &Vg[row * HD + c * 4]);
        }
        if (tid < FKT) {
            CP_ASYNC4(sbase + (F_MSK + buf * FKT + tid) * 4, &mb[kt * FKT + tid]);
        }
    };

    stage(0, 0);
    CP_ASYNC_COMMIT();

    uint32_t* Pw = (uint32_t*)(smf + F_PSM + w * 32 * KVS);

    for (int kt = 0; kt < FNT; kt++) {
        if (kt + 1 < FNT) {
            stage(kt + 1, (kt + 1) & 1);
            CP_ASYNC_COMMIT();
            CP_ASYNC_WAIT(1);
        } else {
            CP_ASYNC_WAIT(0);
        }
        __syncthreads();

        const int buf = kt & 1;
        const float* Kbuf = smf + F_KSM + buf * FKT * KVS;
        const float* Vbuf = smf + F_VSM + buf * FKT * KVS;
        const int* mk = smi + F_MSK + buf * FKT;

        float sc[2][8][4];
#pragma unroll
        for (int mi = 0; mi < 2; mi++)
#pragma unroll
            for (int j = 0; j < 8; j++)
#pragma unroll
                for (int c = 0; c < 4; c++) sc[mi][j][c] = 0.f;
#pragma unroll
        for (int s = 0; s < 8; s++) {
#pragma unroll
            for (int jn = 0; jn < 8; jn++) {
                uint32_t bf[2];
                bf[0] = __float_as_uint(Kbuf[(8 * jn + g) * KVS + 8 * s + tig]);
                bf[1] = __float_as_uint(Kbuf[(8 * jn + g) * KVS + 8 * s + tig + 4]);
                MMA_TF32(sc[0][jn], aQ[0][s], bf);
                MMA_TF32(sc[1][jn], aQ[1][s], bf);
            }
        }

#pragma unroll
        for (int mi = 0; mi < 2; mi++) {
#pragma unroll
            for (int jn = 0; jn < 8; jn++) {
                int2 mv = *(const int2*)&mk[8 * jn + 2 * tig];
                float ax = mv.x ? -1e30f : 0.f;
                float ay = mv.y ? -1e30f : 0.f;
                sc[mi][jn][0] = fmaf(sc[mi][jn][0], CS, ax);
                sc[mi][jn][1] = fmaf(sc[mi][jn][1], CS, ay);
                sc[mi][jn][2] = fmaf(sc[mi][jn][2], CS, ax);
                sc[mi][jn][3] = fmaf(sc[mi][jn][3], CS, ay);
            }
            float mx0 = -1e30f, mx1 = -1e30f;
#pragma unroll
            for (int jn = 0; jn < 8; jn++) {
                mx0 = fmaxf(mx0, fmaxf(sc[mi][jn][0], sc[mi][jn][1]));
                mx1 = fmaxf(mx1, fmaxf(sc[mi][jn][2], sc[mi][jn][3]));
            }
            mx0 = fmaxf(mx0, __shfl_xor_sync(0xFFFFFFFF, mx0, 1));
            mx0 = fmaxf(mx0, __shfl_xor_sync(0xFFFFFFFF, mx0, 2));
            mx1 = fmaxf(mx1, __shfl_xor_sync(0xFFFFFFFF, mx1, 1));
            mx1 = fmaxf(mx1, __shfl_xor_sync(0xFFFFFFFF, mx1, 2));

            const float nm0 = fmaxf(mrun[2 * mi], mx0);
            const float nm1 = fmaxf(mrun[2 * mi + 1], mx1);
            const float cor0 = fast_exp2(mrun[2 * mi] - nm0);
            const float cor1 = fast_exp2(mrun[2 * mi + 1] - nm1);
            mrun[2 * mi] = nm0;
            mrun[2 * mi + 1] = nm1;

            float s0 = 0.f, s1 = 0.f;
#pragma unroll
            for (int jn = 0; jn < 8; jn++) {
                sc[mi][jn][0] = fast_exp2(sc[mi][jn][0] - nm0);
                sc[mi][jn][1] = fast_exp2(sc[mi][jn][1] - nm0);
                sc[mi][jn][2] = fast_exp2(sc[mi][jn][2] - nm1);
                sc[mi][jn][3] = fast_exp2(sc[mi][jn][3] - nm1);
                s0 += sc[mi][jn][0] + sc[mi][jn][1];
                s1 += sc[mi][jn][2] + sc[mi][jn][3];
            }
            s0 += __shfl_xor_sync(0xFFFFFFFF, s0, 1);
            s0 += __shfl_xor_sync(0xFFFFFFFF, s0, 2);
            s1 += __shfl_xor_sync(0xFFFFFFFF, s1, 1);
            s1 += __shfl_xor_sync(0xFFFFFFFF, s1, 2);
            lrun[2 * mi] = lrun[2 * mi] * cor0 + s0;
            lrun[2 * mi + 1] = lrun[2 * mi + 1] * cor1 + s1;

#pragma unroll
            for (int j = 0; j < 8; j++) {
                oacc[mi][j][0] *= cor0;
                oacc[mi][j][1] *= cor0;
                oacc[mi][j][2] *= cor1;
                oacc[mi][j][3] *= cor1;
            }

#pragma unroll
            for (int jn = 0; jn < 8; jn++) {
                Pw[(16 * mi + g) * KVS + 8 * jn + 2 * tig]           = f2tf32(sc[mi][jn][0]);
                Pw[(16 * mi + g) * KVS + 8 * jn + 2 * tig + 1]       = f2tf32(sc[mi][jn][1]);
                Pw[(16 * mi + g + 8) * KVS + 8 * jn + 2 * tig]       = f2tf32(sc[mi][jn][2]);
                Pw[(16 * mi + g + 8) * KVS + 8 * jn + 2 * tig + 1]   = f2tf32(sc[mi][jn][3]);
            }
        }
        __syncwarp();

#pragma unroll
        for (int s2 = 0; s2 < 8; s2++) {
            uint32_t pa0[4], pa1[4];
            pa0[0] = Pw[g * KVS + 8 * s2 + tig];
            pa0[1] = Pw[(g + 8) * KVS + 8 * s2 + tig];
            pa0[2] = Pw[g * KVS + 8 * s2 + tig + 4];
            pa0[3] = Pw[(g + 8) * KVS + 8 * s2 + tig + 4];
            pa1[0] = Pw[(g + 16) * KVS + 8 * s2 + tig];
            pa1[1] = Pw[(g + 24) * KVS + 8 * s2 + tig];
            pa1[2] = Pw[(g + 16) * KVS + 8 * s2 + tig + 4];
            pa1[3] = Pw[(g + 24) * KVS + 8 * s2 + tig + 4];
#pragma unroll
            for (int jn2 = 0; jn2 < 8; jn2++) {
                uint32_t bf[2];
                bf[0] = __float_as_uint(Vbuf[(8 * s2 + tig) * KVS + 8 * jn2 + g]);
                bf[1] = __float_as_uint(Vbuf[(8 * s2 + tig + 4) * KVS + 8 * jn2 + g]);
                MMA_TF32(oacc[0][jn2], pa0, bf);
                MMA_TF32(oacc[1][jn2], pa1, bf);
            }
        }
        __syncthreads();
    }

#pragma unroll
    for (int mi = 0; mi < 2; mi++) {
        const float il0 = 1.f / lrun[2 * mi];
        const float il1 = 1.f / lrun[2 * mi + 1];
        float* O0 = Out + ((size_t)(b * SEQ + qr0 + 16 * mi + g)) * DIM + h * HD;
        float* O1 = Out + ((size_t)(b * SEQ + qr0 + 16 * mi + g + 8)) * DIM + h * HD;
#pragma unroll
        for (int jn2 = 0; jn2 < 8; jn2++) {
            float2 r0, r1;
            r0.x = __uint_as_float(f2tf32(oacc[mi][jn2][0] * il0));
            r0.y = __uint_as_float(f2tf32(oacc[mi][jn2][1] * il0));
            r1.x = __uint_as_float(f2tf32(oacc[mi][jn2][2] * il1));
            r1.y = __uint_as_float(f2tf32(oacc[mi][jn2][3] * il1));
            *(float2*)&O0[8 * jn2 + 2 * tig] = r0;
            *(float2*)&O1[8 * jn2 + 2 * tig] = r1;
        }
    }
}

// ---------------------------------------------------------------------------
extern "C" void kernel_launch(void* const* d_in, const int* in_sizes, int n_in,
                              void* d_out, int out_size) {
    const float* q  = (const float*)d_in[0];
    const float* k  = (const float*)d_in[1];
    const float* v  = (const float*)d_in[2];
    const int* mask = (const int*)d_in[3];
    const float* Wq = (const float*)d_in[4];
    const float* bq = (const float*)d_in[5];
    const float* Wk = (const float*)d_in[6];
    const float* bk = (const float*)d_in[7];
    const float* Wv = (const float*)d_in[8];
    const float* bv = (const float*)d_in[9];
    const float* Wo = (const float*)d_in[10];
    const float* bo = (const float*)d_in[11];
    float* out = (float*)d_out;

    float *pQ, *pK, *pV, *pA, *pWc, *pXc;
    cudaGetSymbolAddress((void**)&pQ, g_Q);
    cudaGetSymbolAddress((void**)&pK, g_K);
    cudaGetSymbolAddress((void**)&pV, g_V);
    cudaGetSymbolAddress((void**)&pA, g_A);
    cudaGetSymbolAddress((void**)&pWc, g_Wc);
    cudaGetSymbolAddress((void**)&pXc, g_Xc);

    cudaFuncSetAttribute(gemm_qkv, cudaFuncAttributeMaxDynamicSharedMemorySize, SM_GEMM_TOTAL);
    cudaFuncSetAttribute(gemm_out, cudaFuncAttributeMaxDynamicSharedMemorySize, SM_GEMM_TOTAL);
    cudaFuncSetAttribute(flash_attn_tc, cudaFuncAttributeMaxDynamicSharedMemorySize, FLASH_SMEM_BYTES);

    // --- fused tf32 pre-rounding: one launch for all 7 arrays ---
    const int W4 = DIM * DIM / 4;       // 262144
    const int X4 = MROWS * DIM / 4;     // 1048576
    ConvArgs ca;
    ca.src[0] = Wq; ca.dst[0] = pWc + 0 * DIM * DIM; ca.n4[0] = W4;
    ca.src[1] = Wk; ca.dst[1] = pWc + 1 * DIM * DIM; ca.n4[1] = W4;
    ca.src[2] = Wv; ca.dst[2] = pWc + 2 * DIM * DIM; ca.n4[2] = W4;
    ca.src[3] = Wo; ca.dst[3] = pWc + 3 * DIM * DIM; ca.n4[3] = W4;
    ca.src[4] = q;  ca.dst[4] = pXc + 0 * (size_t)MROWS * DIM; ca.n4[4] = X4;
    ca.src[5] = k;  ca.dst[5] = pXc + 1 * (size_t)MROWS * DIM; ca.n4[5] = X4;
    ca.src[6] = v;  ca.dst[6] = pXc + 2 * (size_t)MROWS * DIM; ca.n4[6] = X4;
    conv_tf32_all<<<dim3(X4 / 1024, 7), 256>>>(ca);

    GemmArgs aq{pXc + 0 * (size_t)MROWS * DIM, pWc + 0 * DIM * DIM, bq, pQ};
    GemmArgs ak{pXc + 1 * (size_t)MROWS * DIM, pWc + 1 * DIM * DIM, bk, pK};
    GemmArgs av{pXc + 2 * (size_t)MROWS * DIM, pWc + 2 * DIM * DIM, bv, pV};

    dim3 gqkv(DIM / GBN, MROWS / GBM, 3);   // 384 CTAs
    gemm_qkv<<<gqkv, 512, SM_GEMM_TOTAL>>>(aq, ak, av);

    flash_attn_tc<<<dim3(SEQ / 128, NH, BATCH), 128, FLASH_SMEM_BYTES>>>(mask, pA);

    dim3 go(DIM / GBN, MROWS / GBM);        // 128 CTAs
    gemm_out<<<go, 512, SM_GEMM_TOTAL>>>(pA, pWc + 3 * DIM * DIM, bo, out);
}